// round 14
// baseline (speedup 1.0000x reference)
#include <cuda_runtime.h>
#include <cuda_fp16.h>
#include <cstdint>

#define NC 5
#define NU 6144
#define NV 6144
#define ND 64
#define NB 4096
#define CAPM 448   // merged per-node list capacity: mean 307, sigma 17.4 -> 8 sigma
#define NWRD 192   // u-words per (c,v) bitmap row (6144/32)

// ---------------- scratch (static device globals; no runtime allocation) ----
__device__ __align__(16) __half g_msg_a[NC * NV * ND];   // fp16 messages [C,V,D]
__device__ __align__(16) __half g_msg_b[NC * NU * ND];   // fp16 messages [C,U,D]
__device__ __align__(16) float g_hu[NU * ND];
__device__ __align__(16) float g_hv[NV * ND];
__device__ __align__(16) float g_zu[NU * ND];
__device__ __align__(16) float g_zv[NV * ND];
// rowcnt: zero at load; re-zeroed by k_dec each run. colcnt: overwritten by k_cext.
__device__ int g_rowcnt[NU];
__device__ int g_colcnt[NV];
__device__ __align__(16) unsigned short g_rowlist[NU * CAPM];  // value = c*NV+v
__device__ __align__(16) unsigned short g_collist[NV * CAPM];  // value = c*NU+u
// col bitmap [c][v][u/32]; zero at load; k_cext re-zeroes consumed words
__device__ __align__(16) unsigned g_colbm[NC * NV * NWRD];

// ---------------- bit-cast helpers ------------------------------------------
__device__ __forceinline__ unsigned h2u(half2 h) {
    return *reinterpret_cast<unsigned*>(&h);
}
__device__ __forceinline__ half2 u2h(unsigned u) {
    return *reinterpret_cast<half2*>(&u);
}

// ---------------- adjacency build: per-lane extraction ----------------------
__device__ __forceinline__ void ldg256(const char* p, unsigned long long& a,
                                       unsigned long long& b, unsigned long long& c,
                                       unsigned long long& d) {
    asm("ld.global.nc.v4.b64 {%0, %1, %2, %3}, [%4];"
        : "=l"(a), "=l"(b), "=l"(c), "=l"(d) : "l"(p));
}

#define NTILE  737280u   // (NC*NU*NV)/256
#define TPC    147456u   // (NU*NV)/256 tiles per class
#define TPR    24u       // tiles per adjacency row (6144/256)

#define T1_BLKS    960u
#define BUILD_BLKS 1184u
#define FUSED_GRID (T1_BLKS + BUILD_BLKS)

__device__ __forceinline__ void process_tile(unsigned tile, unsigned long long a,
                                             unsigned long long b, unsigned long long c,
                                             unsigned long long d, int lane) {
    if ((a | b | c | d) == 0ull) return;   // fast path: 92% of lanes

    unsigned msk = 0;
    msk |= ((unsigned)a         != 0u) ? 0x01u : 0u;
    msk |= ((unsigned)(a >> 32) != 0u) ? 0x02u : 0u;
    msk |= ((unsigned)b         != 0u) ? 0x04u : 0u;
    msk |= ((unsigned)(b >> 32) != 0u) ? 0x08u : 0u;
    msk |= ((unsigned)c         != 0u) ? 0x10u : 0u;
    msk |= ((unsigned)(c >> 32) != 0u) ? 0x20u : 0u;
    msk |= ((unsigned)d         != 0u) ? 0x40u : 0u;
    msk |= ((unsigned)(d >> 32) != 0u) ? 0x80u : 0u;

    unsigned cls = tile / TPC;
    unsigned rt  = tile - cls * TPC;          // tile within class
    unsigned uu  = rt / TPR;                  // constant row for the tile
    unsigned vb  = (rt - uu * TPR) * 256u + (unsigned)lane * 8u;
    unsigned crow = cls * (unsigned)NV;
    unsigned wofs = uu >> 5;                  // u-word within bitmap row
    unsigned ubit = 1u << (uu & 31u);

    int cnt = __popc(msk);
    int s = atomicAdd(&g_rowcnt[uu], cnt);    // one aggregated row atomic/lane
    unsigned rl = uu * CAPM;
    while (msk) {
        int k = __ffs(msk) - 1;
        msk &= msk - 1u;
        unsigned vv = vb + (unsigned)k;
        if (s < CAPM) g_rowlist[rl + s] = (unsigned short)(crow + vv);
        s++;
        // col side: fire-and-forget RED.OR into the bitmap (no return chain)
        atomicOr(&g_colbm[(size_t)(crow + vv) * NWRD + wofs], ubit);
    }
}

// rotating 3-buffer pipeline: no register moves in steady state
__device__ void build_body(const float* __restrict__ adj, unsigned bbid) {
    int lane = threadIdx.x & 31;
    unsigned warp = (bbid * 256u + threadIdx.x) >> 5;
    const unsigned nwarp = (BUILD_BLKS * 256u) >> 5;   // 9472
    const char* base = (const char*)adj + (unsigned)lane * 32u;

    unsigned t = warp;
    unsigned long long aA, bA, cA, dA, aB, bB, cB, dB, aC, bC, cC, dC;
    ldg256(base + (size_t)t * 1024u, aA, bA, cA, dA);
    bool hB = (t + nwarp) < NTILE;
    if (hB) ldg256(base + (size_t)(t + nwarp) * 1024u, aB, bB, cB, dB);

    while (true) {
        bool hC = (t + 2u * nwarp) < NTILE;
        if (hC) ldg256(base + (size_t)(t + 2u * nwarp) * 1024u, aC, bC, cC, dC);
        process_tile(t, aA, bA, cA, dA, lane);
        if (!hB) return;
        t += nwarp;

        bool hA = (t + 2u * nwarp) < NTILE;
        if (hA) ldg256(base + (size_t)(t + 2u * nwarp) * 1024u, aA, bA, cA, dA);
        process_tile(t, aB, bB, cB, dB, lane);
        if (!hC) return;
        t += nwarp;

        hB = (t + 2u * nwarp) < NTILE;
        if (hB) ldg256(base + (size_t)(t + 2u * nwarp) * 1024u, aB, bB, cB, dB);
        process_tile(t, aC, bC, cC, dC, lane);
        if (!hA) return;
        t += nwarp;
    }
}

// ---------------- per-class dense transform body (fp16 out) -----------------
__device__ __forceinline__ void transform_body(
    int bx, int c, int z,
    const float* __restrict__ X0, const float* __restrict__ W0, __half* __restrict__ out0,
    const float* __restrict__ X1, const float* __restrict__ W1, __half* __restrict__ out1,
    int N) {
    __shared__ __align__(16) float Xs[64 * 65];
    __shared__ __align__(16) float Ws[64 * 64];
    int tid = threadIdx.x;               // 256 threads
    int n0 = bx * 64;
    const float* X = (z == 0) ? X0 : X1;
    const float* W = (z == 0) ? W0 : W1;
    __half* out = (z == 0) ? out0 : out1;

    const float4* X4 = (const float4*)(X + (size_t)n0 * ND);
    const float4* W4 = (const float4*)(W + (size_t)c * ND * ND);
#pragma unroll
    for (int r = 0; r < 4; r++) {
        int f = tid + r * 256;
        float4 xv = X4[f];
        int n = f >> 4, q = f & 15;
        Xs[n * 65 + 4 * q + 0] = xv.x;
        Xs[n * 65 + 4 * q + 1] = xv.y;
        Xs[n * 65 + 4 * q + 2] = xv.z;
        Xs[n * 65 + 4 * q + 3] = xv.w;
        ((float4*)Ws)[f] = W4[f];
    }
    __syncthreads();

    int te = tid & 15, tn = tid >> 4;
    float a00=0,a01=0,a02=0,a03=0, a10=0,a11=0,a12=0,a13=0;
    float a20=0,a21=0,a22=0,a23=0, a30=0,a31=0,a32=0,a33=0;
#pragma unroll 8
    for (int d = 0; d < 64; d++) {
        float4 w = *(const float4*)&Ws[d * 64 + te * 4];
        float x0 = Xs[(tn * 4 + 0) * 65 + d];
        float x1 = Xs[(tn * 4 + 1) * 65 + d];
        float x2 = Xs[(tn * 4 + 2) * 65 + d];
        float x3 = Xs[(tn * 4 + 3) * 65 + d];
        a00 += x0 * w.x; a01 += x0 * w.y; a02 += x0 * w.z; a03 += x0 * w.w;
        a10 += x1 * w.x; a11 += x1 * w.y; a12 += x1 * w.z; a13 += x1 * w.w;
        a20 += x2 * w.x; a21 += x2 * w.y; a22 += x2 * w.z; a23 += x2 * w.w;
        a30 += x3 * w.x; a31 += x3 * w.y; a32 += x3 * w.z; a33 += x3 * w.w;
    }
    __half* ob = out + ((size_t)c * N + n0 + tn * 4) * ND + te * 4;
    *(uint2*)(ob + 0 * ND) = make_uint2(h2u(__floats2half2_rn(a00, a01)),
                                        h2u(__floats2half2_rn(a02, a03)));
    *(uint2*)(ob + 1 * ND) = make_uint2(h2u(__floats2half2_rn(a10, a11)),
                                        h2u(__floats2half2_rn(a12, a13)));
    *(uint2*)(ob + 2 * ND) = make_uint2(h2u(__floats2half2_rn(a20, a21)),
                                        h2u(__floats2half2_rn(a22, a23)));
    *(uint2*)(ob + 3 * ND) = make_uint2(h2u(__floats2half2_rn(a30, a31)),
                                        h2u(__floats2half2_rn(a32, a33)));
}

// ---------------- fused: adjacency build + layer-1 transforms ---------------
__global__ void __launch_bounds__(256, 4)
k_fused1(const float* __restrict__ adj,
         const float* __restrict__ Xv, const float* __restrict__ W1v, __half* __restrict__ msg_a,
         const float* __restrict__ Xu, const float* __restrict__ W1u, __half* __restrict__ msg_b) {
    unsigned bid = blockIdx.x;
    bool is_t = (bid < 2u * T1_BLKS) && ((bid & 1u) == 0u);
    if (is_t) {
        unsigned tb = bid >> 1;                 // 0..959
        int bx = tb % 96;
        unsigned r = tb / 96;
        int c = r % NC, z = r / NC;
        transform_body(bx, c, z, Xv, W1v, msg_a, Xu, W1u, msg_b, NV);
    } else {
        unsigned bb = (bid < 2u * T1_BLKS) ? (bid >> 1) : (bid - T1_BLKS);
        build_body(adj, bb);
    }
}

// ---------------- col-list extraction from bitmap (atomic-free) -------------
// One warp owns column v: sequential slots via register-cumulative count +
// warp prefix scan. Re-zeroes consumed nonzero words (restores invariant).
__global__ void k_cext(void) {
    int lane = threadIdx.x & 31;
    int v = blockIdx.x * 8 + (threadIdx.x >> 5);
    if (v >= NV) return;

    int tot = 0;
    unsigned short* cl = g_collist + (size_t)v * CAPM;
#pragma unroll
    for (int cls = 0; cls < NC; cls++) {
        unsigned* bmrow = g_colbm + (size_t)(cls * NV + v) * NWRD;
        unsigned ccol = (unsigned)(cls * NU);
#pragma unroll
        for (int b = 0; b < NWRD; b += 32) {
            unsigned w = bmrow[b + lane];
            int cnt = __popc(w);
            int pre = cnt;
#pragma unroll
            for (int o = 1; o < 32; o <<= 1) {
                int t = __shfl_up_sync(0xffffffffu, pre, o);
                if (lane >= o) pre += t;
            }
            int bt = __shfl_sync(0xffffffffu, pre, 31);
            int s = tot + pre - cnt;
            if (w) {
                bmrow[b + lane] = 0;            // restore zero invariant
                unsigned ub = (unsigned)(b + lane) * 32u;
                do {
                    int k = __ffs(w) - 1;
                    w &= w - 1u;
                    if (s < CAPM) cl[s] = (unsigned short)(ccol + ub + (unsigned)k);
                    s++;
                } while (w);
            }
            tot += bt;
        }
    }
    if (lane == 0) g_colcnt[v] = tot;
}

// ---------------- standalone transform (layer 2) ----------------------------
__global__ void k_transform2(const float* __restrict__ X0, const float* __restrict__ W0,
                             __half* __restrict__ out0,
                             const float* __restrict__ X1, const float* __restrict__ W1,
                             __half* __restrict__ out1, int N) {
    transform_body(blockIdx.x, blockIdx.y, blockIdx.z, X0, W0, out0, X1, W1, out1, N);
}

// ---------------- merged sparse aggregation over fp16 messages --------------
__device__ __forceinline__ void hacc(float4& a, uint2 p) {
    float2 lo = __half22float2(u2h(p.x));
    float2 hi = __half22float2(u2h(p.y));
    a.x += lo.x; a.y += lo.y; a.z += hi.x; a.w += hi.y;
}

__global__ void k_gather2(float* __restrict__ outA, const __half* __restrict__ msgA,
                          const float* __restrict__ biasA,
                          float* __restrict__ outB, const __half* __restrict__ msgB,
                          const float* __restrict__ biasB, int do_relu) {
    __shared__ __align__(16) unsigned short sidx[4][CAPM];
    int warp = threadIdx.x >> 5, lane = threadIdx.x & 31;
    int node = blockIdx.x * 4 + warp;
    bool sideA = node < NU;
    int u = sideA ? node : node - NU;
    const __half* msg = sideA ? msgA : msgB;
    const float* bias = sideA ? biasA : biasB;
    float* out = sideA ? outA : outB;
    const int* cnt = sideA ? g_rowcnt : g_colcnt;
    const unsigned short* lists = sideA ? g_rowlist : g_collist;

    int m = cnt[u];
    if (m > CAPM) m = CAPM;

    const uint4* lg = (const uint4*)(lists + (size_t)u * CAPM);
    uint4* ls = (uint4*)sidx[warp];
    for (int k = lane; k * 8 < m; k += 32) ls[k] = lg[k];
    __syncwarp();

    int hw = lane >> 4;
    int l4 = lane & 15;
    float4 acc = make_float4(0.f, 0.f, 0.f, 0.f);
    if (hw == 0) {
#pragma unroll
        for (int c = 0; c < NC; c++) {
            float4 bv = ((const float4*)(bias + c * ND))[l4];
            acc.x += bv.x; acc.y += bv.y; acc.z += bv.z; acc.w += bv.w;
        }
    }

    const uint2* mg = (const uint2*)msg;
    const unsigned short* si = sidx[warp];
    int mm = m & ~7;
    for (int b = 0; b < mm; b += 8) {
        unsigned o0 = si[b + 0 + hw];
        unsigned o1 = si[b + 2 + hw];
        unsigned o2 = si[b + 4 + hw];
        unsigned o3 = si[b + 6 + hw];
        uint2 p0 = mg[o0 * 16u + l4];
        uint2 p1 = mg[o1 * 16u + l4];
        uint2 p2 = mg[o2 * 16u + l4];
        uint2 p3 = mg[o3 * 16u + l4];
        hacc(acc, p0); hacc(acc, p1); hacc(acc, p2); hacc(acc, p3);
    }
    for (int b = mm; b < m; b += 2) {
        int e = b + hw;
        if (e < m) {
            uint2 p = mg[(unsigned)si[e] * 16u + l4];
            hacc(acc, p);
        }
    }
    acc.x += __shfl_xor_sync(0xffffffffu, acc.x, 16);
    acc.y += __shfl_xor_sync(0xffffffffu, acc.y, 16);
    acc.z += __shfl_xor_sync(0xffffffffu, acc.z, 16);
    acc.w += __shfl_xor_sync(0xffffffffu, acc.w, 16);
    if (hw == 0) {
        if (do_relu) {
            acc.x = fmaxf(acc.x, 0.f); acc.y = fmaxf(acc.y, 0.f);
            acc.z = fmaxf(acc.z, 0.f); acc.w = fmaxf(acc.w, 0.f);
        }
        ((float4*)(out + (size_t)u * ND))[l4] = acc;
    }
}

// ---------------- fused decoder: (zu[ui] @ Q[c]) . zv[vi] -> logits ---------
// Also re-zeroes g_rowcnt (last kernel; globals start zeroed at load).
__global__ void k_dec(const float* __restrict__ Q, const int* __restrict__ ui,
                      const int* __restrict__ vi, float* __restrict__ out) {
    int zb = blockIdx.y * 64 + blockIdx.x;        // grid (64, 5) -> 320 blocks
    if (zb < 24) g_rowcnt[zb * 256 + threadIdx.x] = 0;   // 24*256 = 6144

    __shared__ __align__(16) float Xs[64 * 65];
    __shared__ __align__(16) float Ws[64 * 64];
    int tid = threadIdx.x;
    int c = blockIdx.y;
    int n0 = blockIdx.x * 64;

    const float4* W4 = (const float4*)(Q + (size_t)c * ND * ND);
#pragma unroll
    for (int r = 0; r < 4; r++) {
        int f = tid + r * 256;
        int n = f >> 4, q = f & 15;
        int row = ui[n0 + n];
        float4 xv = ((const float4*)(g_zu + (size_t)row * ND))[q];
        Xs[n * 65 + 4 * q + 0] = xv.x;
        Xs[n * 65 + 4 * q + 1] = xv.y;
        Xs[n * 65 + 4 * q + 2] = xv.z;
        Xs[n * 65 + 4 * q + 3] = xv.w;
        ((float4*)Ws)[f] = W4[f];
    }
    __syncthreads();

    int te = tid & 15, tn = tid >> 4;
    float a00=0,a01=0,a02=0,a03=0, a10=0,a11=0,a12=0,a13=0;
    float a20=0,a21=0,a22=0,a23=0, a30=0,a31=0,a32=0,a33=0;
#pragma unroll 8
    for (int d = 0; d < 64; d++) {
        float4 w = *(const float4*)&Ws[d * 64 + te * 4];
        float x0 = Xs[(tn * 4 + 0) * 65 + d];
        float x1 = Xs[(tn * 4 + 1) * 65 + d];
        float x2 = Xs[(tn * 4 + 2) * 65 + d];
        float x3 = Xs[(tn * 4 + 3) * 65 + d];
        a00 += x0 * w.x; a01 += x0 * w.y; a02 += x0 * w.z; a03 += x0 * w.w;
        a10 += x1 * w.x; a11 += x1 * w.y; a12 += x1 * w.z; a13 += x1 * w.w;
        a20 += x2 * w.x; a21 += x2 * w.y; a22 += x2 * w.z; a23 += x2 * w.w;
        a30 += x3 * w.x; a31 += x3 * w.y; a32 += x3 * w.z; a33 += x3 * w.w;
    }
#pragma unroll
    for (int r = 0; r < 4; r++) {
        int b = n0 + tn * 4 + r;
        int v = vi[b];
        float4 zvv = ((const float4*)(g_zv + (size_t)v * ND))[te];
        float p;
        if (r == 0)      p = a00 * zvv.x + a01 * zvv.y + a02 * zvv.z + a03 * zvv.w;
        else if (r == 1) p = a10 * zvv.x + a11 * zvv.y + a12 * zvv.z + a13 * zvv.w;
        else if (r == 2) p = a20 * zvv.x + a21 * zvv.y + a22 * zvv.z + a23 * zvv.w;
        else             p = a30 * zvv.x + a31 * zvv.y + a32 * zvv.z + a33 * zvv.w;
#pragma unroll
        for (int o = 8; o; o >>= 1) p += __shfl_xor_sync(0xffffffffu, p, o);
        if (te == 0) out[b * NC + c] = p;
    }
}

// ---------------- launcher ---------------------------------------------------
extern "C" void kernel_launch(void* const* d_in, const int* in_sizes, int n_in,
                              void* d_out, int out_size) {
    const int*   ui    = (const int*)d_in[0];
    const int*   vi    = (const int*)d_in[1];
    const float* u_emb = (const float*)d_in[2];
    const float* v_emb = (const float*)d_in[3];
    const float* W1u   = (const float*)d_in[4];
    const float* b1u   = (const float*)d_in[5];
    const float* W1v   = (const float*)d_in[6];
    const float* b1v   = (const float*)d_in[7];
    const float* W2u   = (const float*)d_in[8];
    const float* b2u   = (const float*)d_in[9];
    const float* W2v   = (const float*)d_in[10];
    const float* b2v   = (const float*)d_in[11];
    const float* Q     = (const float*)d_in[12];
    const float* adj   = (const float*)d_in[13];
    float* out = (float*)d_out;

    __half *msg_a, *msg_b;
    float *hu, *hv, *zu, *zv;
    cudaGetSymbolAddress((void**)&msg_a, g_msg_a);
    cudaGetSymbolAddress((void**)&msg_b, g_msg_b);
    cudaGetSymbolAddress((void**)&hu, g_hu);
    cudaGetSymbolAddress((void**)&hv, g_hv);
    cudaGetSymbolAddress((void**)&zu, g_zu);
    cudaGetSymbolAddress((void**)&zv, g_zv);

    // fused build (row lists + col bitmap) + layer-1 transforms
    k_fused1<<<FUSED_GRID, 256>>>(adj, v_emb, W1v, msg_a, u_emb, W1u, msg_b);

    // col-list extraction (atomic-free, also re-zeroes the bitmap)
    k_cext<<<NV / 8, 256>>>();

    // layer 1 gather
    k_gather2<<<(NU + NV) / 4, 128>>>(hu, msg_a, b1v, hv, msg_b, b1u, 1);

    // layer 2
    k_transform2<<<dim3(96, NC, 2), 256>>>(hv, W2u, msg_a, hu, W2v, msg_b, NV);
    k_gather2<<<(NU + NV) / 4, 128>>>(zu, msg_a, b2u, zv, msg_b, b2v, 0);

    // fused bilinear decoder (also re-zeroes rowcnt for the next run)
    k_dec<<<dim3(64, NC), 256>>>(Q, ui, vi, out);
}

// round 15
// speedup vs baseline: 1.1769x; 1.1769x over previous
#include <cuda_runtime.h>
#include <cuda_fp16.h>
#include <cstdint>

#define NC 5
#define NU 6144
#define NV 6144
#define ND 64
#define NB 4096
#define CAPM 448   // merged per-node list capacity: mean 307, sigma 17.4 -> 8 sigma

// ---------------- scratch (static device globals; no runtime allocation) ----
__device__ __align__(16) __half g_msg_a[NC * NV * ND];   // fp16 messages [C,V,D]
__device__ __align__(16) __half g_msg_b[NC * NU * ND];   // fp16 messages [C,U,D]
__device__ __align__(16) float g_hu[NU * ND];
__device__ __align__(16) float g_hv[NV * ND];
__device__ __align__(16) float g_zu[NU * ND];
__device__ __align__(16) float g_zv[NV * ND];
// cursors + work counter: zero at load; re-zeroed by k_dec every run
__device__ int g_rowcnt[NU];
__device__ int g_colcnt[NV];
__device__ unsigned g_tilectr;
__device__ __align__(16) unsigned short g_rowlist[NU * CAPM];  // value = c*NV+v
__device__ __align__(16) unsigned short g_collist[NV * CAPM];  // value = c*NU+u

// ---------------- bit-cast helpers ------------------------------------------
__device__ __forceinline__ unsigned h2u(half2 h) {
    return *reinterpret_cast<unsigned*>(&h);
}
__device__ __forceinline__ half2 u2h(unsigned u) {
    return *reinterpret_cast<half2*>(&u);
}

// ---------------- adjacency build: work-stealing, per-lane extraction -------
__device__ __forceinline__ void ldg256(const char* p, unsigned long long& a,
                                       unsigned long long& b, unsigned long long& c,
                                       unsigned long long& d) {
    asm("ld.global.nc.v4.b64 {%0, %1, %2, %3}, [%4];"
        : "=l"(a), "=l"(b), "=l"(c), "=l"(d) : "l"(p));
}

#define NTILE  737280u   // (NC*NU*NV)/256
#define TPC    147456u   // (NU*NV)/256 tiles per class
#define TPR    24u       // tiles per adjacency row (6144/256)
#define GRAB   16u       // contiguous tiles per counter grab (NTILE % GRAB == 0)
#define NOTILE 0xFFFFFFFFu

#define T1_BLKS    960u
#define BUILD_BLKS 1184u
#define FUSED_GRID (T1_BLKS + BUILD_BLKS)

__device__ __forceinline__ void process_tile(unsigned tile, unsigned long long a,
                                             unsigned long long b, unsigned long long c,
                                             unsigned long long d, int lane) {
    if ((a | b | c | d) == 0ull) return;   // fast path: 92% of lanes

    unsigned msk = 0;
    msk |= ((unsigned)a         != 0u) ? 0x01u : 0u;
    msk |= ((unsigned)(a >> 32) != 0u) ? 0x02u : 0u;
    msk |= ((unsigned)b         != 0u) ? 0x04u : 0u;
    msk |= ((unsigned)(b >> 32) != 0u) ? 0x08u : 0u;
    msk |= ((unsigned)c         != 0u) ? 0x10u : 0u;
    msk |= ((unsigned)(c >> 32) != 0u) ? 0x20u : 0u;
    msk |= ((unsigned)d         != 0u) ? 0x40u : 0u;
    msk |= ((unsigned)(d >> 32) != 0u) ? 0x80u : 0u;

    unsigned cls = tile / TPC;
    unsigned rt  = tile - cls * TPC;          // tile within class
    unsigned uu  = rt / TPR;                  // constant row for the tile
    unsigned vb  = (rt - uu * TPR) * 256u + (unsigned)lane * 8u;
    unsigned crow = cls * (unsigned)NV;
    unsigned ccol = cls * (unsigned)NU;

    int cnt = __popc(msk);
    int s = atomicAdd(&g_rowcnt[uu], cnt);    // one aggregated row atomic/lane
    unsigned rl = uu * CAPM;
    while (msk) {
        int k = __ffs(msk) - 1;
        msk &= msk - 1u;
        unsigned vv = vb + (unsigned)k;
        if (s < CAPM) g_rowlist[rl + s] = (unsigned short)(crow + vv);
        s++;
        int q = atomicAdd(&g_colcnt[vv], 1);
        if (q < CAPM) g_collist[vv * CAPM + q] = (unsigned short)(ccol + uu);
    }
}

// work-stealing tile stream + rotating 3-buffer load pipeline
__device__ void build_body(const float* __restrict__ adj) {
    int lane = threadIdx.x & 31;
    const char* base = (const char*)adj + (unsigned)lane * 32u;

    // grab sequence state (uniform across warp)
    unsigned cur, nxt, off = 0;
    {
        unsigned g0 = 0, g1 = 0;
        if (lane == 0) g0 = atomicAdd(&g_tilectr, GRAB);
        cur = __shfl_sync(0xffffffffu, g0, 0);
        if (lane == 0) g1 = atomicAdd(&g_tilectr, GRAB);
        nxt = __shfl_sync(0xffffffffu, g1, 0);
    }
    if (cur >= NTILE) return;

    auto adv = [&]() -> unsigned {
        unsigned t = (cur < NTILE) ? (cur + off) : NOTILE;
        if (++off == GRAB) {
            off = 0;
            cur = nxt;
            unsigned g = NTILE;
            if (cur < NTILE) {             // only grab more while work may remain
                if (lane == 0) g = atomicAdd(&g_tilectr, GRAB);
                g = __shfl_sync(0xffffffffu, g, 0);
            }
            nxt = g;
        }
        return t;
    };

    unsigned long long aA, bA, cA, dA, aB, bB, cB, dB, aC, bC, cC, dC;
    unsigned tA = adv();
    ldg256(base + (size_t)tA * 1024u, aA, bA, cA, dA);
    unsigned tB = adv();
    bool hB = tB != NOTILE;
    if (hB) ldg256(base + (size_t)tB * 1024u, aB, bB, cB, dB);
    bool hA, hC;

    while (true) {
        unsigned tC = adv();
        hC = tC != NOTILE;
        if (hC) ldg256(base + (size_t)tC * 1024u, aC, bC, cC, dC);
        process_tile(tA, aA, bA, cA, dA, lane);
        if (!hB) return;

        tA = adv();
        hA = tA != NOTILE;
        if (hA) ldg256(base + (size_t)tA * 1024u, aA, bA, cA, dA);
        process_tile(tB, aB, bB, cB, dB, lane);
        if (!hC) return;

        tB = adv();
        hB = tB != NOTILE;
        if (hB) ldg256(base + (size_t)tB * 1024u, aB, bB, cB, dB);
        process_tile(tC, aC, bC, cC, dC, lane);
        if (!hA) return;
    }
}

// ---------------- per-class dense transform body (fp16 out) -----------------
__device__ __forceinline__ void transform_body(
    int bx, int c, int z,
    const float* __restrict__ X0, const float* __restrict__ W0, __half* __restrict__ out0,
    const float* __restrict__ X1, const float* __restrict__ W1, __half* __restrict__ out1,
    int N) {
    __shared__ __align__(16) float Xs[64 * 65];
    __shared__ __align__(16) float Ws[64 * 64];
    int tid = threadIdx.x;               // 256 threads
    int n0 = bx * 64;
    const float* X = (z == 0) ? X0 : X1;
    const float* W = (z == 0) ? W0 : W1;
    __half* out = (z == 0) ? out0 : out1;

    const float4* X4 = (const float4*)(X + (size_t)n0 * ND);
    const float4* W4 = (const float4*)(W + (size_t)c * ND * ND);
#pragma unroll
    for (int r = 0; r < 4; r++) {
        int f = tid + r * 256;
        float4 xv = X4[f];
        int n = f >> 4, q = f & 15;
        Xs[n * 65 + 4 * q + 0] = xv.x;
        Xs[n * 65 + 4 * q + 1] = xv.y;
        Xs[n * 65 + 4 * q + 2] = xv.z;
        Xs[n * 65 + 4 * q + 3] = xv.w;
        ((float4*)Ws)[f] = W4[f];
    }
    __syncthreads();

    int te = tid & 15, tn = tid >> 4;
    float a00=0,a01=0,a02=0,a03=0, a10=0,a11=0,a12=0,a13=0;
    float a20=0,a21=0,a22=0,a23=0, a30=0,a31=0,a32=0,a33=0;
#pragma unroll 8
    for (int d = 0; d < 64; d++) {
        float4 w = *(const float4*)&Ws[d * 64 + te * 4];
        float x0 = Xs[(tn * 4 + 0) * 65 + d];
        float x1 = Xs[(tn * 4 + 1) * 65 + d];
        float x2 = Xs[(tn * 4 + 2) * 65 + d];
        float x3 = Xs[(tn * 4 + 3) * 65 + d];
        a00 += x0 * w.x; a01 += x0 * w.y; a02 += x0 * w.z; a03 += x0 * w.w;
        a10 += x1 * w.x; a11 += x1 * w.y; a12 += x1 * w.z; a13 += x1 * w.w;
        a20 += x2 * w.x; a21 += x2 * w.y; a22 += x2 * w.z; a23 += x2 * w.w;
        a30 += x3 * w.x; a31 += x3 * w.y; a32 += x3 * w.z; a33 += x3 * w.w;
    }
    __half* ob = out + ((size_t)c * N + n0 + tn * 4) * ND + te * 4;
    *(uint2*)(ob + 0 * ND) = make_uint2(h2u(__floats2half2_rn(a00, a01)),
                                        h2u(__floats2half2_rn(a02, a03)));
    *(uint2*)(ob + 1 * ND) = make_uint2(h2u(__floats2half2_rn(a10, a11)),
                                        h2u(__floats2half2_rn(a12, a13)));
    *(uint2*)(ob + 2 * ND) = make_uint2(h2u(__floats2half2_rn(a20, a21)),
                                        h2u(__floats2half2_rn(a22, a23)));
    *(uint2*)(ob + 3 * ND) = make_uint2(h2u(__floats2half2_rn(a30, a31)),
                                        h2u(__floats2half2_rn(a32, a33)));
}

// ---------------- fused: adjacency build + layer-1 transforms ---------------
__global__ void __launch_bounds__(256, 4)
k_fused1(const float* __restrict__ adj,
         const float* __restrict__ Xv, const float* __restrict__ W1v, __half* __restrict__ msg_a,
         const float* __restrict__ Xu, const float* __restrict__ W1u, __half* __restrict__ msg_b) {
    unsigned bid = blockIdx.x;
    bool is_t = (bid < 2u * T1_BLKS) && ((bid & 1u) == 0u);
    if (is_t) {
        unsigned tb = bid >> 1;                 // 0..959
        int bx = tb % 96;
        unsigned r = tb / 96;
        int c = r % NC, z = r / NC;
        transform_body(bx, c, z, Xv, W1v, msg_a, Xu, W1u, msg_b, NV);
    } else {
        build_body(adj);
    }
}

// ---------------- standalone transform (layer 2) ----------------------------
__global__ void k_transform2(const float* __restrict__ X0, const float* __restrict__ W0,
                             __half* __restrict__ out0,
                             const float* __restrict__ X1, const float* __restrict__ W1,
                             __half* __restrict__ out1, int N) {
    transform_body(blockIdx.x, blockIdx.y, blockIdx.z, X0, W0, out0, X1, W1, out1, N);
}

// ---------------- merged sparse aggregation over fp16 messages --------------
__device__ __forceinline__ void hacc(float4& a, uint2 p) {
    float2 lo = __half22float2(u2h(p.x));
    float2 hi = __half22float2(u2h(p.y));
    a.x += lo.x; a.y += lo.y; a.z += hi.x; a.w += hi.y;
}

__global__ void k_gather2(float* __restrict__ outA, const __half* __restrict__ msgA,
                          const float* __restrict__ biasA,
                          float* __restrict__ outB, const __half* __restrict__ msgB,
                          const float* __restrict__ biasB, int do_relu) {
    __shared__ __align__(16) unsigned short sidx[4][CAPM];
    int warp = threadIdx.x >> 5, lane = threadIdx.x & 31;
    int node = blockIdx.x * 4 + warp;
    bool sideA = node < NU;
    int u = sideA ? node : node - NU;
    const __half* msg = sideA ? msgA : msgB;
    const float* bias = sideA ? biasA : biasB;
    float* out = sideA ? outA : outB;
    const int* cnt = sideA ? g_rowcnt : g_colcnt;
    const unsigned short* lists = sideA ? g_rowlist : g_collist;

    int m = cnt[u];
    if (m > CAPM) m = CAPM;

    const uint4* lg = (const uint4*)(lists + (size_t)u * CAPM);
    uint4* ls = (uint4*)sidx[warp];
    for (int k = lane; k * 8 < m; k += 32) ls[k] = lg[k];
    __syncwarp();

    int hw = lane >> 4;
    int l4 = lane & 15;
    float4 acc = make_float4(0.f, 0.f, 0.f, 0.f);
    if (hw == 0) {
#pragma unroll
        for (int c = 0; c < NC; c++) {
            float4 bv = ((const float4*)(bias + c * ND))[l4];
            acc.x += bv.x; acc.y += bv.y; acc.z += bv.z; acc.w += bv.w;
        }
    }

    const uint2* mg = (const uint2*)msg;
    const unsigned short* si = sidx[warp];
    int mm = m & ~7;
    for (int b = 0; b < mm; b += 8) {
        unsigned o0 = si[b + 0 + hw];
        unsigned o1 = si[b + 2 + hw];
        unsigned o2 = si[b + 4 + hw];
        unsigned o3 = si[b + 6 + hw];
        uint2 p0 = mg[o0 * 16u + l4];
        uint2 p1 = mg[o1 * 16u + l4];
        uint2 p2 = mg[o2 * 16u + l4];
        uint2 p3 = mg[o3 * 16u + l4];
        hacc(acc, p0); hacc(acc, p1); hacc(acc, p2); hacc(acc, p3);
    }
    for (int b = mm; b < m; b += 2) {
        int e = b + hw;
        if (e < m) {
            uint2 p = mg[(unsigned)si[e] * 16u + l4];
            hacc(acc, p);
        }
    }
    acc.x += __shfl_xor_sync(0xffffffffu, acc.x, 16);
    acc.y += __shfl_xor_sync(0xffffffffu, acc.y, 16);
    acc.z += __shfl_xor_sync(0xffffffffu, acc.z, 16);
    acc.w += __shfl_xor_sync(0xffffffffu, acc.w, 16);
    if (hw == 0) {
        if (do_relu) {
            acc.x = fmaxf(acc.x, 0.f); acc.y = fmaxf(acc.y, 0.f);
            acc.z = fmaxf(acc.z, 0.f); acc.w = fmaxf(acc.w, 0.f);
        }
        ((float4*)(out + (size_t)u * ND))[l4] = acc;
    }
}

// ---------------- fused decoder: (zu[ui] @ Q[c]) . zv[vi] -> logits ---------
// Also re-zeroes cursors + work counter (last kernel; globals start zeroed).
__global__ void k_dec(const float* __restrict__ Q, const int* __restrict__ ui,
                      const int* __restrict__ vi, float* __restrict__ out) {
    int zb = blockIdx.y * 64 + blockIdx.x;        // grid (64, 5) -> 320 blocks
    if (zb < 24)      g_rowcnt[zb * 256 + threadIdx.x] = 0;        // 24*256 = 6144
    else if (zb < 48) g_colcnt[(zb - 24) * 256 + threadIdx.x] = 0;
    else if (zb == 48 && threadIdx.x == 0) g_tilectr = 0;

    __shared__ __align__(16) float Xs[64 * 65];
    __shared__ __align__(16) float Ws[64 * 64];
    int tid = threadIdx.x;
    int c = blockIdx.y;
    int n0 = blockIdx.x * 64;

    const float4* W4 = (const float4*)(Q + (size_t)c * ND * ND);
#pragma unroll
    for (int r = 0; r < 4; r++) {
        int f = tid + r * 256;
        int n = f >> 4, q = f & 15;
        int row = ui[n0 + n];
        float4 xv = ((const float4*)(g_zu + (size_t)row * ND))[q];
        Xs[n * 65 + 4 * q + 0] = xv.x;
        Xs[n * 65 + 4 * q + 1] = xv.y;
        Xs[n * 65 + 4 * q + 2] = xv.z;
        Xs[n * 65 + 4 * q + 3] = xv.w;
        ((float4*)Ws)[f] = W4[f];
    }
    __syncthreads();

    int te = tid & 15, tn = tid >> 4;
    float a00=0,a01=0,a02=0,a03=0, a10=0,a11=0,a12=0,a13=0;
    float a20=0,a21=0,a22=0,a23=0, a30=0,a31=0,a32=0,a33=0;
#pragma unroll 8
    for (int d = 0; d < 64; d++) {
        float4 w = *(const float4*)&Ws[d * 64 + te * 4];
        float x0 = Xs[(tn * 4 + 0) * 65 + d];
        float x1 = Xs[(tn * 4 + 1) * 65 + d];
        float x2 = Xs[(tn * 4 + 2) * 65 + d];
        float x3 = Xs[(tn * 4 + 3) * 65 + d];
        a00 += x0 * w.x; a01 += x0 * w.y; a02 += x0 * w.z; a03 += x0 * w.w;
        a10 += x1 * w.x; a11 += x1 * w.y; a12 += x1 * w.z; a13 += x1 * w.w;
        a20 += x2 * w.x; a21 += x2 * w.y; a22 += x2 * w.z; a23 += x2 * w.w;
        a30 += x3 * w.x; a31 += x3 * w.y; a32 += x3 * w.z; a33 += x3 * w.w;
    }
#pragma unroll
    for (int r = 0; r < 4; r++) {
        int b = n0 + tn * 4 + r;
        int v = vi[b];
        float4 zvv = ((const float4*)(g_zv + (size_t)v * ND))[te];
        float p;
        if (r == 0)      p = a00 * zvv.x + a01 * zvv.y + a02 * zvv.z + a03 * zvv.w;
        else if (r == 1) p = a10 * zvv.x + a11 * zvv.y + a12 * zvv.z + a13 * zvv.w;
        else if (r == 2) p = a20 * zvv.x + a21 * zvv.y + a22 * zvv.z + a23 * zvv.w;
        else             p = a30 * zvv.x + a31 * zvv.y + a32 * zvv.z + a33 * zvv.w;
#pragma unroll
        for (int o = 8; o; o >>= 1) p += __shfl_xor_sync(0xffffffffu, p, o);
        if (te == 0) out[b * NC + c] = p;
    }
}

// ---------------- launcher ---------------------------------------------------
extern "C" void kernel_launch(void* const* d_in, const int* in_sizes, int n_in,
                              void* d_out, int out_size) {
    const int*   ui    = (const int*)d_in[0];
    const int*   vi    = (const int*)d_in[1];
    const float* u_emb = (const float*)d_in[2];
    const float* v_emb = (const float*)d_in[3];
    const float* W1u   = (const float*)d_in[4];
    const float* b1u   = (const float*)d_in[5];
    const float* W1v   = (const float*)d_in[6];
    const float* b1v   = (const float*)d_in[7];
    const float* W2u   = (const float*)d_in[8];
    const float* b2u   = (const float*)d_in[9];
    const float* W2v   = (const float*)d_in[10];
    const float* b2v   = (const float*)d_in[11];
    const float* Q     = (const float*)d_in[12];
    const float* adj   = (const float*)d_in[13];
    float* out = (float*)d_out;

    __half *msg_a, *msg_b;
    float *hu, *hv, *zu, *zv;
    cudaGetSymbolAddress((void**)&msg_a, g_msg_a);
    cudaGetSymbolAddress((void**)&msg_b, g_msg_b);
    cudaGetSymbolAddress((void**)&hu, g_hu);
    cudaGetSymbolAddress((void**)&hv, g_hv);
    cudaGetSymbolAddress((void**)&zu, g_zu);
    cudaGetSymbolAddress((void**)&zv, g_zv);

    // fused work-stealing build + layer-1 transforms
    k_fused1<<<FUSED_GRID, 256>>>(adj, v_emb, W1v, msg_a, u_emb, W1u, msg_b);

    // layer 1 gather
    k_gather2<<<(NU + NV) / 4, 128>>>(hu, msg_a, b1v, hv, msg_b, b1u, 1);

    // layer 2
    k_transform2<<<dim3(96, NC, 2), 256>>>(hv, W2u, msg_a, hu, W2v, msg_b, NV);
    k_gather2<<<(NU + NV) / 4, 128>>>(zu, msg_a, b2u, zv, msg_b, b2v, 0);

    // fused bilinear decoder (also resets cursors + work counter)
    k_dec<<<dim3(64, NC), 256>>>(Q, ui, vi, out);
}

// round 16
// speedup vs baseline: 1.2283x; 1.0437x over previous
#include <cuda_runtime.h>
#include <cuda_fp16.h>
#include <cstdint>

#define NC 5
#define NU 6144
#define NV 6144
#define ND 64
#define NB 4096
#define CAPM 448   // merged per-node list capacity: mean 307, sigma 17.4 -> 8 sigma

// ---------------- scratch (static device globals; no runtime allocation) ----
__device__ __align__(16) __half g_msg_a[NC * NV * ND];   // fp16 messages [C,V,D]
__device__ __align__(16) __half g_msg_b[NC * NU * ND];   // fp16 messages [C,U,D]
__device__ __align__(16) float g_hu[NU * ND];
__device__ __align__(16) float g_hv[NV * ND];
__device__ __align__(16) float g_zu[NU * ND];
__device__ __align__(16) float g_zv[NV * ND];
// cursors: zero at load; re-zeroed by k_dec every run
__device__ int g_rowcnt[NU];
__device__ int g_colcnt[NV];
__device__ __align__(16) unsigned short g_rowlist[NU * CAPM];  // value = c*NV+v
__device__ __align__(16) unsigned short g_collist[NV * CAPM];  // value = c*NU+u

// ---------------- bit-cast helpers ------------------------------------------
__device__ __forceinline__ unsigned h2u(half2 h) {
    return *reinterpret_cast<unsigned*>(&h);
}
__device__ __forceinline__ half2 u2h(unsigned u) {
    return *reinterpret_cast<half2*>(&u);
}

// ---------------- adjacency build: per-lane extraction ----------------------
__device__ __forceinline__ void ldg256(const char* p, unsigned long long& a,
                                       unsigned long long& b, unsigned long long& c,
                                       unsigned long long& d) {
    asm("ld.global.nc.v4.b64 {%0, %1, %2, %3}, [%4];"
        : "=l"(a), "=l"(b), "=l"(c), "=l"(d) : "l"(p));
}

#define NTILE  737280u   // (NC*NU*NV)/256
#define TPC    147456u   // (NU*NV)/256 tiles per class
#define TPR    24u       // tiles per adjacency row (6144/256)

#define T1_BLKS    960u
#define BUILD_BLKS 1184u
#define FUSED_GRID (T1_BLKS + BUILD_BLKS)

__device__ __forceinline__ void process_tile(unsigned tile, unsigned long long a,
                                             unsigned long long b, unsigned long long c,
                                             unsigned long long d, int lane) {
    if ((a | b | c | d) == 0ull) return;   // fast path: 92% of lanes

    unsigned msk = 0;
    msk |= ((unsigned)a         != 0u) ? 0x01u : 0u;
    msk |= ((unsigned)(a >> 32) != 0u) ? 0x02u : 0u;
    msk |= ((unsigned)b         != 0u) ? 0x04u : 0u;
    msk |= ((unsigned)(b >> 32) != 0u) ? 0x08u : 0u;
    msk |= ((unsigned)c         != 0u) ? 0x10u : 0u;
    msk |= ((unsigned)(c >> 32) != 0u) ? 0x20u : 0u;
    msk |= ((unsigned)d         != 0u) ? 0x40u : 0u;
    msk |= ((unsigned)(d >> 32) != 0u) ? 0x80u : 0u;

    unsigned cls = tile / TPC;
    unsigned rt  = tile - cls * TPC;          // tile within class
    unsigned uu  = rt / TPR;                  // constant row for the tile
    unsigned vb  = (rt - uu * TPR) * 256u + (unsigned)lane * 8u;
    unsigned crow = cls * (unsigned)NV;
    unsigned ccol = cls * (unsigned)NU;

    int cnt = __popc(msk);
    int s = atomicAdd(&g_rowcnt[uu], cnt);    // one aggregated row atomic/lane
    unsigned rl = uu * CAPM;
    while (msk) {
        int k = __ffs(msk) - 1;
        msk &= msk - 1u;
        unsigned vv = vb + (unsigned)k;
        if (s < CAPM) g_rowlist[rl + s] = (unsigned short)(crow + vv);
        s++;
        int q = atomicAdd(&g_colcnt[vv], 1);
        if (q < CAPM) g_collist[vv * CAPM + q] = (unsigned short)(ccol + uu);
    }
}

// rotating 4-buffer pipeline: three tiles in flight ahead of processing
__device__ void build_body(const float* __restrict__ adj, unsigned bbid) {
    int lane = threadIdx.x & 31;
    unsigned warp = (bbid * 256u + threadIdx.x) >> 5;
    const unsigned nwarp = (BUILD_BLKS * 256u) >> 5;   // 9472
    const char* base = (const char*)adj + (unsigned)lane * 32u;

    unsigned t = warp;
    unsigned long long aA, bA, cA, dA, aB, bB, cB, dB;
    unsigned long long aC, bC, cC, dC, aD, bD, cD, dD;
    ldg256(base + (size_t)t * 1024u, aA, bA, cA, dA);
    bool hB = (t + nwarp) < NTILE;
    if (hB) ldg256(base + (size_t)(t + nwarp) * 1024u, aB, bB, cB, dB);
    bool hC = (t + 2u * nwarp) < NTILE;
    if (hC) ldg256(base + (size_t)(t + 2u * nwarp) * 1024u, aC, bC, cC, dC);
    bool hD, hA;

    while (true) {
        hD = (t + 3u * nwarp) < NTILE;
        if (hD) ldg256(base + (size_t)(t + 3u * nwarp) * 1024u, aD, bD, cD, dD);
        process_tile(t, aA, bA, cA, dA, lane);
        if (!hB) return;
        t += nwarp;

        hA = (t + 3u * nwarp) < NTILE;
        if (hA) ldg256(base + (size_t)(t + 3u * nwarp) * 1024u, aA, bA, cA, dA);
        process_tile(t, aB, bB, cB, dB, lane);
        if (!hC) return;
        t += nwarp;

        hB = (t + 3u * nwarp) < NTILE;
        if (hB) ldg256(base + (size_t)(t + 3u * nwarp) * 1024u, aB, bB, cB, dB);
        process_tile(t, aC, bC, cC, dC, lane);
        if (!hD) return;
        t += nwarp;

        hC = (t + 3u * nwarp) < NTILE;
        if (hC) ldg256(base + (size_t)(t + 3u * nwarp) * 1024u, aC, bC, cC, dC);
        process_tile(t, aD, bD, cD, dD, lane);
        if (!hA) return;
        t += nwarp;
    }
}

// ---------------- per-class dense transform body (fp16 out) -----------------
__device__ __forceinline__ void transform_body(
    int bx, int c, int z,
    const float* __restrict__ X0, const float* __restrict__ W0, __half* __restrict__ out0,
    const float* __restrict__ X1, const float* __restrict__ W1, __half* __restrict__ out1,
    int N) {
    __shared__ __align__(16) float Xs[64 * 65];
    __shared__ __align__(16) float Ws[64 * 64];
    int tid = threadIdx.x;               // 256 threads
    int n0 = bx * 64;
    const float* X = (z == 0) ? X0 : X1;
    const float* W = (z == 0) ? W0 : W1;
    __half* out = (z == 0) ? out0 : out1;

    const float4* X4 = (const float4*)(X + (size_t)n0 * ND);
    const float4* W4 = (const float4*)(W + (size_t)c * ND * ND);
#pragma unroll
    for (int r = 0; r < 4; r++) {
        int f = tid + r * 256;
        float4 xv = X4[f];
        int n = f >> 4, q = f & 15;
        Xs[n * 65 + 4 * q + 0] = xv.x;
        Xs[n * 65 + 4 * q + 1] = xv.y;
        Xs[n * 65 + 4 * q + 2] = xv.z;
        Xs[n * 65 + 4 * q + 3] = xv.w;
        ((float4*)Ws)[f] = W4[f];
    }
    __syncthreads();

    int te = tid & 15, tn = tid >> 4;
    float a00=0,a01=0,a02=0,a03=0, a10=0,a11=0,a12=0,a13=0;
    float a20=0,a21=0,a22=0,a23=0, a30=0,a31=0,a32=0,a33=0;
#pragma unroll 8
    for (int d = 0; d < 64; d++) {
        float4 w = *(const float4*)&Ws[d * 64 + te * 4];
        float x0 = Xs[(tn * 4 + 0) * 65 + d];
        float x1 = Xs[(tn * 4 + 1) * 65 + d];
        float x2 = Xs[(tn * 4 + 2) * 65 + d];
        float x3 = Xs[(tn * 4 + 3) * 65 + d];
        a00 += x0 * w.x; a01 += x0 * w.y; a02 += x0 * w.z; a03 += x0 * w.w;
        a10 += x1 * w.x; a11 += x1 * w.y; a12 += x1 * w.z; a13 += x1 * w.w;
        a20 += x2 * w.x; a21 += x2 * w.y; a22 += x2 * w.z; a23 += x2 * w.w;
        a30 += x3 * w.x; a31 += x3 * w.y; a32 += x3 * w.z; a33 += x3 * w.w;
    }
    __half* ob = out + ((size_t)c * N + n0 + tn * 4) * ND + te * 4;
    *(uint2*)(ob + 0 * ND) = make_uint2(h2u(__floats2half2_rn(a00, a01)),
                                        h2u(__floats2half2_rn(a02, a03)));
    *(uint2*)(ob + 1 * ND) = make_uint2(h2u(__floats2half2_rn(a10, a11)),
                                        h2u(__floats2half2_rn(a12, a13)));
    *(uint2*)(ob + 2 * ND) = make_uint2(h2u(__floats2half2_rn(a20, a21)),
                                        h2u(__floats2half2_rn(a22, a23)));
    *(uint2*)(ob + 3 * ND) = make_uint2(h2u(__floats2half2_rn(a30, a31)),
                                        h2u(__floats2half2_rn(a32, a33)));
}

// ---------------- fused: adjacency build + layer-1 transforms ---------------
__global__ void __launch_bounds__(256, 4)
k_fused1(const float* __restrict__ adj,
         const float* __restrict__ Xv, const float* __restrict__ W1v, __half* __restrict__ msg_a,
         const float* __restrict__ Xu, const float* __restrict__ W1u, __half* __restrict__ msg_b) {
    unsigned bid = blockIdx.x;
    bool is_t = (bid < 2u * T1_BLKS) && ((bid & 1u) == 0u);
    if (is_t) {
        unsigned tb = bid >> 1;                 // 0..959
        int bx = tb % 96;
        unsigned r = tb / 96;
        int c = r % NC, z = r / NC;
        transform_body(bx, c, z, Xv, W1v, msg_a, Xu, W1u, msg_b, NV);
    } else {
        unsigned bb = (bid < 2u * T1_BLKS) ? (bid >> 1) : (bid - T1_BLKS);
        build_body(adj, bb);
    }
}

// ---------------- standalone transform (layer 2) ----------------------------
__global__ void k_transform2(const float* __restrict__ X0, const float* __restrict__ W0,
                             __half* __restrict__ out0,
                             const float* __restrict__ X1, const float* __restrict__ W1,
                             __half* __restrict__ out1, int N) {
    transform_body(blockIdx.x, blockIdx.y, blockIdx.z, X0, W0, out0, X1, W1, out1, N);
}

// ---------------- merged sparse aggregation over fp16 messages --------------
__device__ __forceinline__ void hacc(float4& a, uint2 p) {
    float2 lo = __half22float2(u2h(p.x));
    float2 hi = __half22float2(u2h(p.y));
    a.x += lo.x; a.y += lo.y; a.z += hi.x; a.w += hi.y;
}

__global__ void k_gather2(float* __restrict__ outA, const __half* __restrict__ msgA,
                          const float* __restrict__ biasA,
                          float* __restrict__ outB, const __half* __restrict__ msgB,
                          const float* __restrict__ biasB, int do_relu) {
    __shared__ __align__(16) unsigned short sidx[4][CAPM];
    int warp = threadIdx.x >> 5, lane = threadIdx.x & 31;
    int node = blockIdx.x * 4 + warp;
    bool sideA = node < NU;
    int u = sideA ? node : node - NU;
    const __half* msg = sideA ? msgA : msgB;
    const float* bias = sideA ? biasA : biasB;
    float* out = sideA ? outA : outB;
    const int* cnt = sideA ? g_rowcnt : g_colcnt;
    const unsigned short* lists = sideA ? g_rowlist : g_collist;

    int m = cnt[u];
    if (m > CAPM) m = CAPM;

    const uint4* lg = (const uint4*)(lists + (size_t)u * CAPM);
    uint4* ls = (uint4*)sidx[warp];
    for (int k = lane; k * 8 < m; k += 32) ls[k] = lg[k];
    __syncwarp();

    int hw = lane >> 4;
    int l4 = lane & 15;
    float4 acc = make_float4(0.f, 0.f, 0.f, 0.f);
    if (hw == 0) {
#pragma unroll
        for (int c = 0; c < NC; c++) {
            float4 bv = ((const float4*)(bias + c * ND))[l4];
            acc.x += bv.x; acc.y += bv.y; acc.z += bv.z; acc.w += bv.w;
        }
    }

    const uint2* mg = (const uint2*)msg;
    const unsigned short* si = sidx[warp];
    int mm = m & ~7;
    for (int b = 0; b < mm; b += 8) {
        unsigned o0 = si[b + 0 + hw];
        unsigned o1 = si[b + 2 + hw];
        unsigned o2 = si[b + 4 + hw];
        unsigned o3 = si[b + 6 + hw];
        uint2 p0 = mg[o0 * 16u + l4];
        uint2 p1 = mg[o1 * 16u + l4];
        uint2 p2 = mg[o2 * 16u + l4];
        uint2 p3 = mg[o3 * 16u + l4];
        hacc(acc, p0); hacc(acc, p1); hacc(acc, p2); hacc(acc, p3);
    }
    for (int b = mm; b < m; b += 2) {
        int e = b + hw;
        if (e < m) {
            uint2 p = mg[(unsigned)si[e] * 16u + l4];
            hacc(acc, p);
        }
    }
    acc.x += __shfl_xor_sync(0xffffffffu, acc.x, 16);
    acc.y += __shfl_xor_sync(0xffffffffu, acc.y, 16);
    acc.z += __shfl_xor_sync(0xffffffffu, acc.z, 16);
    acc.w += __shfl_xor_sync(0xffffffffu, acc.w, 16);
    if (hw == 0) {
        if (do_relu) {
            acc.x = fmaxf(acc.x, 0.f); acc.y = fmaxf(acc.y, 0.f);
            acc.z = fmaxf(acc.z, 0.f); acc.w = fmaxf(acc.w, 0.f);
        }
        ((float4*)(out + (size_t)u * ND))[l4] = acc;
    }
}

// ---------------- fused decoder: (zu[ui] @ Q[c]) . zv[vi] -> logits ---------
// Also re-zeroes the build cursors (last kernel; globals start zeroed at load).
__global__ void k_dec(const float* __restrict__ Q, const int* __restrict__ ui,
                      const int* __restrict__ vi, float* __restrict__ out) {
    int zb = blockIdx.y * 64 + blockIdx.x;        // grid (64, 5) -> 320 blocks
    if (zb < 24)      g_rowcnt[zb * 256 + threadIdx.x] = 0;        // 24*256 = 6144
    else if (zb < 48) g_colcnt[(zb - 24) * 256 + threadIdx.x] = 0;

    __shared__ __align__(16) float Xs[64 * 65];
    __shared__ __align__(16) float Ws[64 * 64];
    int tid = threadIdx.x;
    int c = blockIdx.y;
    int n0 = blockIdx.x * 64;

    const float4* W4 = (const float4*)(Q + (size_t)c * ND * ND);
#pragma unroll
    for (int r = 0; r < 4; r++) {
        int f = tid + r * 256;
        int n = f >> 4, q = f & 15;
        int row = ui[n0 + n];
        float4 xv = ((const float4*)(g_zu + (size_t)row * ND))[q];
        Xs[n * 65 + 4 * q + 0] = xv.x;
        Xs[n * 65 + 4 * q + 1] = xv.y;
        Xs[n * 65 + 4 * q + 2] = xv.z;
        Xs[n * 65 + 4 * q + 3] = xv.w;
        ((float4*)Ws)[f] = W4[f];
    }
    __syncthreads();

    int te = tid & 15, tn = tid >> 4;
    float a00=0,a01=0,a02=0,a03=0, a10=0,a11=0,a12=0,a13=0;
    float a20=0,a21=0,a22=0,a23=0, a30=0,a31=0,a32=0,a33=0;
#pragma unroll 8
    for (int d = 0; d < 64; d++) {
        float4 w = *(const float4*)&Ws[d * 64 + te * 4];
        float x0 = Xs[(tn * 4 + 0) * 65 + d];
        float x1 = Xs[(tn * 4 + 1) * 65 + d];
        float x2 = Xs[(tn * 4 + 2) * 65 + d];
        float x3 = Xs[(tn * 4 + 3) * 65 + d];
        a00 += x0 * w.x; a01 += x0 * w.y; a02 += x0 * w.z; a03 += x0 * w.w;
        a10 += x1 * w.x; a11 += x1 * w.y; a12 += x1 * w.z; a13 += x1 * w.w;
        a20 += x2 * w.x; a21 += x2 * w.y; a22 += x2 * w.z; a23 += x2 * w.w;
        a30 += x3 * w.x; a31 += x3 * w.y; a32 += x3 * w.z; a33 += x3 * w.w;
    }
#pragma unroll
    for (int r = 0; r < 4; r++) {
        int b = n0 + tn * 4 + r;
        int v = vi[b];
        float4 zvv = ((const float4*)(g_zv + (size_t)v * ND))[te];
        float p;
        if (r == 0)      p = a00 * zvv.x + a01 * zvv.y + a02 * zvv.z + a03 * zvv.w;
        else if (r == 1) p = a10 * zvv.x + a11 * zvv.y + a12 * zvv.z + a13 * zvv.w;
        else if (r == 2) p = a20 * zvv.x + a21 * zvv.y + a22 * zvv.z + a23 * zvv.w;
        else             p = a30 * zvv.x + a31 * zvv.y + a32 * zvv.z + a33 * zvv.w;
#pragma unroll
        for (int o = 8; o; o >>= 1) p += __shfl_xor_sync(0xffffffffu, p, o);
        if (te == 0) out[b * NC + c] = p;
    }
}

// ---------------- launcher ---------------------------------------------------
extern "C" void kernel_launch(void* const* d_in, const int* in_sizes, int n_in,
                              void* d_out, int out_size) {
    const int*   ui    = (const int*)d_in[0];
    const int*   vi    = (const int*)d_in[1];
    const float* u_emb = (const float*)d_in[2];
    const float* v_emb = (const float*)d_in[3];
    const float* W1u   = (const float*)d_in[4];
    const float* b1u   = (const float*)d_in[5];
    const float* W1v   = (const float*)d_in[6];
    const float* b1v   = (const float*)d_in[7];
    const float* W2u   = (const float*)d_in[8];
    const float* b2u   = (const float*)d_in[9];
    const float* W2v   = (const float*)d_in[10];
    const float* b2v   = (const float*)d_in[11];
    const float* Q     = (const float*)d_in[12];
    const float* adj   = (const float*)d_in[13];
    float* out = (float*)d_out;

    __half *msg_a, *msg_b;
    float *hu, *hv, *zu, *zv;
    cudaGetSymbolAddress((void**)&msg_a, g_msg_a);
    cudaGetSymbolAddress((void**)&msg_b, g_msg_b);
    cudaGetSymbolAddress((void**)&hu, g_hu);
    cudaGetSymbolAddress((void**)&hv, g_hv);
    cudaGetSymbolAddress((void**)&zu, g_zu);
    cudaGetSymbolAddress((void**)&zv, g_zv);

    // fused build (4-deep pipeline) + layer-1 transforms
    k_fused1<<<FUSED_GRID, 256>>>(adj, v_emb, W1v, msg_a, u_emb, W1u, msg_b);

    // layer 1 gather
    k_gather2<<<(NU + NV) / 4, 128>>>(hu, msg_a, b1v, hv, msg_b, b1u, 1);

    // layer 2
    k_transform2<<<dim3(96, NC, 2), 256>>>(hv, W2u, msg_a, hu, W2v, msg_b, NV);
    k_gather2<<<(NU + NV) / 4, 128>>>(zu, msg_a, b2u, zv, msg_b, b2v, 0);

    // fused bilinear decoder (also re-zeroes cursors for the next run)
    k_dec<<<dim3(64, NC), 256>>>(Q, ui, vi, out);
}